// round 8
// baseline (speedup 1.0000x reference)
#include <cuda_runtime.h>
#include <cuda_bf16.h>
#include <cuda_fp16.h>
#include <math.h>
#include <stdint.h>

// Problem constants
#define BB 2
#define MM 2048
#define DD 1024
#define HH 16
#define DH 64
#define FF 2624
#define NTOK (BB*MM)           // 4096
#define QKV_N (3*DD)           // 3072
#define WI_N (2*FF)            // 5248

// ---------------- scratch (device globals; no allocation allowed) -------------
__device__ float g_q   [NTOK*DD];        // [B,H,M,DH] fp32 (pre-rope)
__device__ float g_k   [NTOK*DD];
__device__ float g_v   [NTOK*DD];
__device__ float g_xres[NTOK*DD];
__device__ float g_g   [NTOK*WI_N];
__device__ float2 g_rope[MM*32];         // (cos,sin) per (m, i)
// bf16x3 split buffers
__device__ __align__(128) __nv_bfloat16 g_a3[(size_t)NTOK * 3 * FF];
__device__ __align__(128) __nv_bfloat16 g_w3[(size_t)WI_N * 3 * DD];
// f16 attention operands [B,H,M,DH]
__device__ __align__(128) __half g_q2[(size_t)BB*HH*MM*DH];
__device__ __align__(128) __half g_k2[(size_t)BB*HH*MM*DH];
__device__ __align__(128) __half g_v2[(size_t)BB*HH*MM*DH];

// ---------------- PTX helpers (base compute_80 features only) -----------------
__device__ __forceinline__ uint32_t smem_u32(const void* p) {
    uint32_t a;
    asm("{ .reg .u64 t; cvta.to.shared.u64 t, %1; cvt.u32.u64 %0, t; }"
        : "=r"(a) : "l"(p));
    return a;
}
__device__ __forceinline__ void cp16(uint32_t saddr, const void* g) {
    asm volatile("cp.async.cg.shared.global [%0], [%1], 16;" :: "r"(saddr), "l"(g));
}
__device__ __forceinline__ void ldm_x4(uint32_t* r, uint32_t addr) {
    asm volatile("ldmatrix.sync.aligned.m8n8.x4.shared.b16 {%0,%1,%2,%3}, [%4];"
        : "=r"(r[0]), "=r"(r[1]), "=r"(r[2]), "=r"(r[3]) : "r"(addr));
}
__device__ __forceinline__ void ldm_x4_t(uint32_t* r, uint32_t addr) {
    asm volatile("ldmatrix.sync.aligned.m8n8.x4.trans.shared.b16 {%0,%1,%2,%3}, [%4];"
        : "=r"(r[0]), "=r"(r[1]), "=r"(r[2]), "=r"(r[3]) : "r"(addr));
}
__device__ __forceinline__ void mma16816(float* c, const uint32_t* a, const uint32_t* b) {
    asm volatile("mma.sync.aligned.m16n8k16.row.col.f32.bf16.bf16.f32 "
        "{%0,%1,%2,%3}, {%4,%5,%6,%7}, {%8,%9}, {%0,%1,%2,%3};"
        : "+f"(c[0]), "+f"(c[1]), "+f"(c[2]), "+f"(c[3])
        : "r"(a[0]), "r"(a[1]), "r"(a[2]), "r"(a[3]), "r"(b[0]), "r"(b[1]));
}
__device__ __forceinline__ void mma16816h(float* c, const uint32_t* a, const uint32_t* b) {
    asm volatile("mma.sync.aligned.m16n8k16.row.col.f32.f16.f16.f32 "
        "{%0,%1,%2,%3}, {%4,%5,%6,%7}, {%8,%9}, {%0,%1,%2,%3};"
        : "+f"(c[0]), "+f"(c[1]), "+f"(c[2]), "+f"(c[3])
        : "r"(a[0]), "r"(a[1]), "r"(a[2]), "r"(a[3]), "r"(b[0]), "r"(b[1]));
}
__device__ __forceinline__ uint32_t cvt_h2(float hi, float lo) {
    uint32_t d;
    asm("cvt.rn.f16x2.f32 %0, %1, %2;" : "=r"(d) : "f"(hi), "f"(lo));
    return d;
}
__device__ __forceinline__ uint32_t h2exp2(uint32_t x) {
    uint32_t d;
    asm("ex2.approx.f16x2 %0, %1;" : "=r"(d) : "r"(x));
    return d;
}
// bf16x3 element write: activation layout [hi | lo | hi], row stride 3K
__device__ __forceinline__ void write_a3_pair(__nv_bfloat16* rowp, int c, int K,
                                              float x, float y) {
    __nv_bfloat162 hi; hi.x = __float2bfloat16(x); hi.y = __float2bfloat16(y);
    __nv_bfloat162 lo;
    lo.x = __float2bfloat16(x - __bfloat162float(hi.x));
    lo.y = __float2bfloat16(y - __bfloat162float(hi.y));
    *(__nv_bfloat162*)(rowp + c)         = hi;
    *(__nv_bfloat162*)(rowp + c + K)     = lo;
    *(__nv_bfloat162*)(rowp + c + 2*K)   = hi;
}

// ---------------- fp32 -> bf16x3 split (weights) -------------------------------
__global__ void splitw_kernel(const float* __restrict__ X,
                              __nv_bfloat16* __restrict__ Y,
                              int K, int total)
{
    int i = blockIdx.x * 256 + threadIdx.x;
    if (i >= total) return;
    int r = i / K;
    int c = i - r * K;
    float x = X[i];
    __nv_bfloat16 hb = __float2bfloat16(x);
    float h = __bfloat162float(hb);
    __nv_bfloat16 lb = __float2bfloat16(x - h);
    size_t base = (size_t)r * (3 * K) + c;
    Y[base] = hb;
    Y[base + K] = hb;
    Y[base + 2*K] = lb;
}

// ---------------- bf16 tensor-core GEMM, 256x128 tile, 4-stage pipeline -------
// 8 warps (4m x 2n), warp tile 64x64, K-tile 32.
// MODE 0: C = acc; MODE 1: QKV scatter + bias; MODE 2: C = acc + resid
#define PADK 40
#define STAGES 4
#define A_BYTES (256*PADK*2)                // 20480
#define B_BYTES (128*PADK*2)                // 10240
#define STAGE_BYTES (A_BYTES + B_BYTES)     // 30720
#define BG_SMEM (STAGES*STAGE_BYTES)        // 122880

template<int MODE>
__global__ __launch_bounds__(256) void bgemm_kernel(
    const __nv_bfloat16* __restrict__ A3, const __nv_bfloat16* __restrict__ W3,
    const float* __restrict__ bias, const float* __restrict__ resid,
    float* __restrict__ C,
    float* __restrict__ qout, float* __restrict__ kout, float* __restrict__ vout,
    int Ndim, int K3)
{
    extern __shared__ char dynsmem[];
    const uint32_t base = smem_u32(dynsmem);

    const int tid = threadIdx.x;
    const int wid = tid >> 5, lid = tid & 31;
    const int wm = wid >> 1, wn = wid & 1;
    const int m0 = blockIdx.y * 256, n0 = blockIdx.x * 128;

    const __nv_bfloat16* Ag = A3 + (size_t)m0 * K3;
    const __nv_bfloat16* Wg = W3 + (size_t)n0 * K3;
    const int ntiles = K3 >> 5;

    // load mapping: 384 rows x 4 chunks = 1536 cp16 / 256 threads = 6 each.
    // j 0..3 -> A rows (tid + j*256)>>2 ; j 4..5 -> B rows idx>>2 - 256
    const int ldc = (tid & 3) * 8;

    float acc[4][8][4];
    #pragma unroll
    for (int i = 0; i < 4; i++)
        #pragma unroll
        for (int j = 0; j < 8; j++)
            #pragma unroll
            for (int x = 0; x < 4; x++) acc[i][j][x] = 0.f;

    const int aRowBase = (wm*64 + (lid & 15)) * PADK + (lid >> 4) * 8;
    const int bRowBase = (wn*64 + ((lid >> 4) & 1) * 8 + (lid & 7)) * PADK
                       + ((lid >> 3) & 1) * 8;

    // prologue: stages 0..2
    #pragma unroll
    for (int t = 0; t < STAGES - 1; t++) {
        uint32_t sb = base + (uint32_t)t * STAGE_BYTES;
        const __nv_bfloat16* Agt = Ag + (size_t)t * 32;
        const __nv_bfloat16* Wgt = Wg + (size_t)t * 32;
        #pragma unroll
        for (int j = 0; j < 6; j++) {
            int idx = tid + j * 256;
            int row = idx >> 2;
            if (row < 256)
                cp16(sb + (uint32_t)(row*PADK + ldc)*2, Agt + (size_t)row*K3 + ldc);
            else
                cp16(sb + A_BYTES + (uint32_t)((row-256)*PADK + ldc)*2,
                     Wgt + (size_t)(row-256)*K3 + ldc);
        }
        asm volatile("cp.async.commit_group;");
    }

    for (int t = 0; t < ntiles; t++) {
        asm volatile("cp.async.wait_group %0;" :: "n"(STAGES - 2));
        __syncthreads();

        if (t + STAGES - 1 < ntiles) {
            int tp = t + STAGES - 1;
            uint32_t sb = base + (uint32_t)(tp & (STAGES-1)) * STAGE_BYTES;
            const __nv_bfloat16* Agt = Ag + (size_t)tp * 32;
            const __nv_bfloat16* Wgt = Wg + (size_t)tp * 32;
            #pragma unroll
            for (int j = 0; j < 6; j++) {
                int idx = tid + j * 256;
                int row = idx >> 2;
                if (row < 256)
                    cp16(sb + (uint32_t)(row*PADK + ldc)*2, Agt + (size_t)row*K3 + ldc);
                else
                    cp16(sb + A_BYTES + (uint32_t)((row-256)*PADK + ldc)*2,
                         Wgt + (size_t)(row-256)*K3 + ldc);
            }
        }
        asm volatile("cp.async.commit_group;");

        uint32_t aS = base + (uint32_t)(t & (STAGES-1)) * STAGE_BYTES;
        uint32_t bS = aS + A_BYTES;

        #pragma unroll
        for (int ks = 0; ks < 2; ks++) {
            uint32_t afr[4][4];
            #pragma unroll
            for (int mt = 0; mt < 4; mt++)
                ldm_x4(afr[mt], aS + (uint32_t)(aRowBase + mt*16*PADK + ks*16) * 2);
            uint32_t bfr[4][4];
            #pragma unroll
            for (int np = 0; np < 4; np++)
                ldm_x4(bfr[np], bS + (uint32_t)(bRowBase + np*16*PADK + ks*16) * 2);
            #pragma unroll
            for (int mt = 0; mt < 4; mt++)
                #pragma unroll
                for (int np = 0; np < 4; np++) {
                    mma16816(acc[mt][2*np],     afr[mt], &bfr[np][0]);
                    mma16816(acc[mt][2*np + 1], afr[mt], &bfr[np][2]);
                }
        }
    }

    #pragma unroll
    for (int mt = 0; mt < 4; mt++) {
        int rbase = m0 + wm*64 + mt*16 + (lid >> 2);
        #pragma unroll
        for (int nt = 0; nt < 8; nt++) {
            int c = n0 + wn*64 + nt*8 + (lid & 3)*2;
            #pragma unroll
            for (int half = 0; half < 2; half++) {
                int n = rbase + half*8;
                float v0 = acc[mt][nt][2*half + 0];
                float v1 = acc[mt][nt][2*half + 1];
                if (MODE == 1) {
                    int b = n >> 11, m = n & 2047;
                    int which = c >> 10, rem = c & 1023;
                    int hh = rem >> 6, d0 = rem & 63;
                    float* dst = ((which == 0) ? qout : (which == 1) ? kout : vout)
                               + ((size_t)(((b << 4) + hh) * MM + m)) * DH + d0;
                    float2 o; o.x = v0 + bias[c]; o.y = v1 + bias[c + 1];
                    *(float2*)dst = o;
                } else {
                    float* cr = C + (size_t)n * Ndim + c;
                    if (MODE == 2) {
                        const float2 rv = *(const float2*)(resid + (size_t)n * Ndim + c);
                        v0 += rv.x; v1 += rv.y;
                    }
                    float2 o; o.x = v0; o.y = v1;
                    *(float2*)cr = o;
                }
            }
        }
    }
}

// ---------------- LayerNorm -> bf16x3 directly --------------------------------
__inline__ __device__ float warpsum(float v) {
    #pragma unroll
    for (int o = 16; o; o >>= 1) v += __shfl_xor_sync(0xffffffff, v, o);
    return v;
}

__global__ __launch_bounds__(256) void ln_kernel(
    const float* __restrict__ x, const float* __restrict__ w,
    const float* __restrict__ b, __nv_bfloat16* __restrict__ a3)
{
    __shared__ float red[2][8];
    int row = blockIdx.x;
    const float4* xr = (const float4*)(x + (size_t)row * DD);
    float4 v = xr[threadIdx.x];
    float s  = v.x + v.y + v.z + v.w;
    float ss = v.x*v.x + v.y*v.y + v.z*v.z + v.w*v.w;
    s = warpsum(s); ss = warpsum(ss);
    int wid = threadIdx.x >> 5, lid = threadIdx.x & 31;
    if (lid == 0) { red[0][wid] = s; red[1][wid] = ss; }
    __syncthreads();
    if (wid == 0) {
        float a = (lid < 8) ? red[0][lid] : 0.f;
        float c = (lid < 8) ? red[1][lid] : 0.f;
        a = warpsum(a); c = warpsum(c);
        if (lid == 0) { red[0][0] = a; red[1][0] = c; }
    }
    __syncthreads();
    float mean = red[0][0] * (1.0f/DD);
    float var  = red[1][0] * (1.0f/DD) - mean*mean;
    float rstd = rsqrtf(var + 1e-5f);
    float4 wv = ((const float4*)w)[threadIdx.x];
    float4 bv = ((const float4*)b)[threadIdx.x];
    float o0 = (v.x - mean)*rstd*wv.x + bv.x;
    float o1 = (v.y - mean)*rstd*wv.y + bv.y;
    float o2 = (v.z - mean)*rstd*wv.z + bv.z;
    float o3 = (v.w - mean)*rstd*wv.w + bv.w;
    __nv_bfloat16* rowp = a3 + (size_t)row * (3*DD);
    int c = threadIdx.x * 4;
    write_a3_pair(rowp, c,     DD, o0, o1);
    write_a3_pair(rowp, c + 2, DD, o2, o3);
}

// ---------------- RoPE table + apply ------------------------------------------
__global__ void ropetab_kernel(float2* __restrict__ tab)
{
    int gid = blockIdx.x * 256 + threadIdx.x;     // over MM*32
    int i = gid & 31;
    int m = gid >> 5;
    float invf = (float)exp2(-(double)i * (13.287712379549449 / 32.0));
    float angle = (float)m * invf;
    float sv, cv;
    sincosf(angle, &sv, &cv);
    tab[gid] = make_float2(cv, sv);
}

#define QSCALE 0.18033688011112042f   // 0.125 * log2(e)
__global__ void rope_kernel(const float* __restrict__ q, const float* __restrict__ k,
                            const float* __restrict__ v,
                            const float2* __restrict__ tab,
                            __half* __restrict__ q2, __half* __restrict__ k2,
                            __half* __restrict__ v2)
{
    int gid = blockIdx.x * blockDim.x + threadIdx.x;   // over B*H*M*32
    int i = gid & 31;
    int r = gid >> 5;
    int m = r & (MM - 1);
    float2 cs = tab[(m << 5) | i];
    float cv = cs.x, sv = cs.y;
    size_t base = (size_t)r * DH + i;
    float q1 = q[base], qq2 = q[base + 32];
    q2[base]      = __float2half((q1 * cv - qq2 * sv) * QSCALE);
    q2[base + 32] = __float2half((q1 * sv + qq2 * cv) * QSCALE);
    float k1 = k[base], kk2 = k[base + 32];
    k2[base]      = __float2half(k1 * cv - kk2 * sv);
    k2[base + 32] = __float2half(k1 * sv + kk2 * cv);
    v2[base]      = __float2half(v[base]);
    v2[base + 32] = __float2half(v[base + 32]);
}

// ---------------- Flash attention: f16 mma.sync, epilogue -> bf16x3 -----------
#define ASTR 72
__global__ __launch_bounds__(128) void attn_kernel(
    const __half* __restrict__ Q2, const __half* __restrict__ K2,
    const __half* __restrict__ V2, const int* __restrict__ amask,
    __nv_bfloat16* __restrict__ a3)
{
    __shared__ __half Qs[64][ASTR];
    __shared__ __half Ks[2][64][ASTR];
    __shared__ __half Vs[2][64][ASTR];
    __shared__ __half2 Ms[2][32];

    const int tid = threadIdx.x, wid = tid >> 5, lid = tid & 31;
    const int bh = blockIdx.y;
    const int b = bh >> 4, h = bh & 15;
    const int q0 = blockIdx.x * 64;

    uint32_t qB = smem_u32(Qs);
    uint32_t kB = smem_u32(Ks);
    uint32_t vB = smem_u32(Vs);

    const __half* Qg = Q2 + ((size_t)bh * MM + q0) * DH;
    const __half* Kg = K2 + (size_t)bh * MM * DH;
    const __half* Vg = V2 + (size_t)bh * MM * DH;

    #pragma unroll
    for (int j = 0; j < 4; j++) {
        int idx = tid + j * 128;
        int row = idx >> 3, ch = (idx & 7) * 8;
        cp16(qB + (row*ASTR + ch)*2, Qg + row*DH + ch);
        cp16(kB + (row*ASTR + ch)*2, Kg + row*DH + ch);
        cp16(vB + (row*ASTR + ch)*2, Vg + row*DH + ch);
    }
    if (tid < 32) {
        int ka = amask[b*MM + 2*tid], kb2 = amask[b*MM + 2*tid + 1];
        Ms[0][tid] = __halves2half2(__int2half_rn(ka ? 1 : 0), __int2half_rn(kb2 ? 1 : 0));
    }
    asm volatile("cp.async.commit_group;");

    float o[8][4];
    #pragma unroll
    for (int f = 0; f < 8; f++)
        #pragma unroll
        for (int j = 0; j < 4; j++) o[f][j] = 0.f;
    float lr0 = 0.f, lr1 = 0.f;

    const uint32_t aAddrBase = qB + ((uint32_t)(wid*16 + (lid & 15)) * ASTR + (lid >> 4) * 8) * 2;
    const uint32_t bRowOff = ((uint32_t)(((lid >> 4) & 1) * 8 + (lid & 7)) * ASTR + ((lid >> 3) & 1) * 8) * 2;
    const uint32_t vRowOff = ((uint32_t)(lid & 15) * ASTR + (lid >> 4) * 8) * 2;

    for (int kt = 0; kt < 32; kt++) {
        int s = kt & 1;
        if (kt + 1 < 32) {
            int s2 = s ^ 1;
            const __half* Kn = Kg + (size_t)(kt + 1) * 64 * DH;
            const __half* Vn = Vg + (size_t)(kt + 1) * 64 * DH;
            #pragma unroll
            for (int j = 0; j < 4; j++) {
                int idx = tid + j * 128;
                int row = idx >> 3, ch = (idx & 7) * 8;
                cp16(kB + (s2*64*ASTR + row*ASTR + ch)*2, Kn + row*DH + ch);
                cp16(vB + (s2*64*ASTR + row*ASTR + ch)*2, Vn + row*DH + ch);
            }
            if (tid < 32) {
                int kbase = b*MM + (kt + 1)*64;
                int ka = amask[kbase + 2*tid], kb2 = amask[kbase + 2*tid + 1];
                Ms[s2][tid] = __halves2half2(__int2half_rn(ka ? 1 : 0), __int2half_rn(kb2 ? 1 : 0));
            }
            asm volatile("cp.async.commit_group;");
            asm volatile("cp.async.wait_group 1;");
        } else {
            asm volatile("cp.async.wait_group 0;");
        }
        __syncthreads();

        uint32_t kS = kB + (uint32_t)s * 64 * ASTR * 2;
        uint32_t vS = vB + (uint32_t)s * 64 * ASTR * 2;

        float sacc[8][4];
        #pragma unroll
        for (int f = 0; f < 8; f++)
            #pragma unroll
            for (int j = 0; j < 4; j++) sacc[f][j] = 0.f;

        #pragma unroll
        for (int kk = 0; kk < 4; kk++) {
            uint32_t aq[4];
            ldm_x4(aq, aAddrBase + (uint32_t)(kk * 16) * 2);
            #pragma unroll
            for (int np = 0; np < 4; np++) {
                uint32_t bk[4];
                ldm_x4(bk, kS + (uint32_t)(np * 16) * ASTR * 2 + bRowOff + (uint32_t)(kk * 16) * 2);
                mma16816h(sacc[2*np],     aq, &bk[0]);
                mma16816h(sacc[2*np + 1], aq, &bk[2]);
            }
        }

        uint32_t p0[8], p1[8];
        __half2 l2a = __halves2half2(__float2half(0.f), __float2half(0.f));
        __half2 l2b = l2a;
        #pragma unroll
        for (int f = 0; f < 8; f++) {
            __half2 m2 = Ms[s][4*f + (lid & 3)];
            uint32_t e0u = h2exp2(cvt_h2(sacc[f][1], sacc[f][0]));
            uint32_t e1u = h2exp2(cvt_h2(sacc[f][3], sacc[f][2]));
            __half2 e0 = __hmul2(*reinterpret_cast<__half2*>(&e0u), m2);
            __half2 e1 = __hmul2(*reinterpret_cast<__half2*>(&e1u), m2);
            p0[f] = *(uint32_t*)&e0;
            p1[f] = *(uint32_t*)&e1;
            l2a = __hadd2(l2a, e0);
            l2b = __hadd2(l2b, e1);
        }
        lr0 += __low2float(l2a) + __high2float(l2a);
        lr1 += __low2float(l2b) + __high2float(l2b);

        #pragma unroll
        for (int kk = 0; kk < 4; kk++) {
            uint32_t A[4] = { p0[2*kk], p1[2*kk], p0[2*kk + 1], p1[2*kk + 1] };
            #pragma unroll
            for (int np = 0; np < 4; np++) {
                uint32_t bv[4];
                ldm_x4_t(bv, vS + (uint32_t)(kk * 16) * ASTR * 2 + vRowOff + (uint32_t)(np * 16) * 2);
                mma16816h(o[2*np],     A, &bv[0]);
                mma16816h(o[2*np + 1], A, &bv[2]);
            }
        }
        __syncthreads();
    }

    lr0 += __shfl_xor_sync(0xffffffff, lr0, 1);
    lr0 += __shfl_xor_sync(0xffffffff, lr0, 2);
    lr1 += __shfl_xor_sync(0xffffffff, lr1, 1);
    lr1 += __shfl_xor_sync(0xffffffff, lr1, 2);
    float inv0 = 1.0f / lr0, inv1 = 1.0f / lr1;

    int gm0 = q0 + wid*16 + (lid >> 2);
    int gm1 = gm0 + 8;
    __nv_bfloat16* r0p = a3 + (size_t)(b * MM + gm0) * (3*DD) + h * DH;
    __nv_bfloat16* r1p = a3 + (size_t)(b * MM + gm1) * (3*DD) + h * DH;
    #pragma unroll
    for (int f = 0; f < 8; f++) {
        int c = 8*f + (lid & 3)*2;
        write_a3_pair(r0p, c, DD, o[f][0]*inv0, o[f][1]*inv0);
        write_a3_pair(r1p, c, DD, o[f][2]*inv1, o[f][3]*inv1);
    }
}

// ---------------- GeGLU -> bf16x3 directly ------------------------------------
__global__ void geglu_kernel(const float* __restrict__ g, __nv_bfloat16* __restrict__ a3)
{
    int n = blockIdx.x;
    const float* gr = g + (size_t)n * WI_N;
    __nv_bfloat16* rowp = a3 + (size_t)n * (3*FF);
    for (int f = threadIdx.x * 2; f < FF; f += blockDim.x * 2) {
        float2 x2 = *(const float2*)(gr + f);
        float2 gt = *(const float2*)(gr + f + FF);
        float v0 = 0.5f * x2.x * (1.0f + erff(x2.x * 0.7071067811865476f)) * gt.x;
        float v1 = 0.5f * x2.y * (1.0f + erff(x2.y * 0.7071067811865476f)) * gt.y;
        write_a3_pair(rowp, f, FF, v0, v1);
    }
}

// ---------------- launch ------------------------------------------------------
extern "C" void kernel_launch(void* const* d_in, const int* in_sizes, int n_in,
                              void* d_out, int out_size)
{
    const float* hs     = (const float*)d_in[0];
    const int*   amask  = (const int*)  d_in[1];
    const float* ln1w   = (const float*)d_in[2];
    const float* ln1b   = (const float*)d_in[3];
    const float* wqkv_w = (const float*)d_in[4];
    const float* wqkv_b = (const float*)d_in[5];
    const float* wo_w   = (const float*)d_in[6];
    const float* ln2w   = (const float*)d_in[7];
    const float* ln2b   = (const float*)d_in[8];
    const float* wi_w   = (const float*)d_in[9];
    const float* womlp  = (const float*)d_in[10];
    float* out = (float*)d_out;

    float *q, *k, *v, *xres, *gg;
    float2* rtab;
    __nv_bfloat16 *a3, *w3;
    __half *q2, *k2, *v2;
    cudaGetSymbolAddress((void**)&q,    g_q);
    cudaGetSymbolAddress((void**)&k,    g_k);
    cudaGetSymbolAddress((void**)&v,    g_v);
    cudaGetSymbolAddress((void**)&xres, g_xres);
    cudaGetSymbolAddress((void**)&gg,   g_g);
    cudaGetSymbolAddress((void**)&rtab, g_rope);
    cudaGetSymbolAddress((void**)&a3,   g_a3);
    cudaGetSymbolAddress((void**)&w3,   g_w3);
    cudaGetSymbolAddress((void**)&q2,   g_q2);
    cudaGetSymbolAddress((void**)&k2,   g_k2);
    cudaGetSymbolAddress((void**)&v2,   g_v2);

    cudaFuncSetAttribute(bgemm_kernel<0>, cudaFuncAttributeMaxDynamicSharedMemorySize, BG_SMEM);
    cudaFuncSetAttribute(bgemm_kernel<1>, cudaFuncAttributeMaxDynamicSharedMemorySize, BG_SMEM);
    cudaFuncSetAttribute(bgemm_kernel<2>, cudaFuncAttributeMaxDynamicSharedMemorySize, BG_SMEM);

    // 0. RoPE table (independent; overlaps nothing but is tiny)
    ropetab_kernel<<<(MM*32)/256, 256>>>(rtab);

    // 1. LN1 -> a3 (bf16x3)
    ln_kernel<<<NTOK, 256>>>(hs, ln1w, ln1b, a3);

    // 2. QKV gemm -> q/k/v fp32
    {
        int totw = QKV_N * DD;
        splitw_kernel<<<(totw + 255)/256, 256>>>(wqkv_w, w3, DD, totw);
        bgemm_kernel<1><<<dim3(QKV_N/128, NTOK/256), 256, BG_SMEM>>>(
            a3, w3, wqkv_b, nullptr, nullptr, q, k, v, QKV_N, 3*DD);
    }

    // 3. RoPE + f16 conversion
    rope_kernel<<<(BB*HH*MM*32)/256, 256>>>(q, k, v, rtab, q2, k2, v2);

    // 4. Flash attention -> a3 (bf16x3 of attention output)
    attn_kernel<<<dim3(MM/64, BB*HH), 128>>>(q2, k2, v2, amask, a3);

    // 5. O projection + residual -> xres
    {
        int totw = DD * DD;
        splitw_kernel<<<(totw + 255)/256, 256>>>(wo_w, w3, DD, totw);
        bgemm_kernel<2><<<dim3(DD/128, NTOK/256), 256, BG_SMEM>>>(
            a3, w3, nullptr, hs, xres, nullptr, nullptr, nullptr, DD, 3*DD);
    }

    // 6. LN2 -> a3
    ln_kernel<<<NTOK, 256>>>(xres, ln2w, ln2b, a3);

    // 7. Wi gemm -> gg fp32
    {
        int totw = WI_N * DD;
        splitw_kernel<<<(totw + 255)/256, 256>>>(wi_w, w3, DD, totw);
        bgemm_kernel<0><<<dim3(WI_N/128, NTOK/256), 256, BG_SMEM>>>(
            a3, w3, nullptr, nullptr, gg, nullptr, nullptr, nullptr, WI_N, 3*DD);
    }

    // 8. GeGLU -> a3 (K=FF layout)
    geglu_kernel<<<NTOK, 256>>>(gg, a3);

    // 9. Wo_mlp gemm + residual -> out
    {
        int totw = DD * FF;
        splitw_kernel<<<(totw + 255)/256, 256>>>(womlp, w3, FF, totw);
        bgemm_kernel<2><<<dim3(DD/128, NTOK/256), 256, BG_SMEM>>>(
            a3, w3, nullptr, xres, out, nullptr, nullptr, nullptr, DD, 3*FF);
    }
}

// round 11
// speedup vs baseline: 1.2779x; 1.2779x over previous
#include <cuda_runtime.h>
#include <cuda_bf16.h>
#include <cuda_fp16.h>
#include <math.h>
#include <stdint.h>

// Problem constants
#define BB 2
#define MM 2048
#define DD 1024
#define HH 16
#define DH 64
#define FF 2624
#define NTOK (BB*MM)           // 4096
#define QKV_N (3*DD)           // 3072
#define WI_N (2*FF)            // 5248

// ---------------- scratch (device globals; no allocation allowed) -------------
__device__ float g_xres[NTOK*DD];
__device__ float g_g   [NTOK*WI_N];
__device__ float2 g_rope[MM*32];         // (cos,sin) per (m, i)
// bf16x3 split buffers
__device__ __align__(128) __nv_bfloat16 g_a3[(size_t)NTOK * 3 * FF];
__device__ __align__(128) __nv_bfloat16 g_w3[(size_t)WI_N * 3 * DD];
// f16 buffers
__device__ __align__(128) __half g_xh[(size_t)NTOK*DD];          // LN1 out f16
__device__ __align__(128) __half g_wh[(size_t)QKV_N*DD];         // wqkv f16
__device__ __align__(128) __half g_q2[(size_t)BB*HH*MM*DH];
__device__ __align__(128) __half g_k2[(size_t)BB*HH*MM*DH];
__device__ __align__(128) __half g_v2[(size_t)BB*HH*MM*DH];

// ---------------- PTX helpers (base compute_80 features only) -----------------
__device__ __forceinline__ uint32_t smem_u32(const void* p) {
    uint32_t a;
    asm("{ .reg .u64 t; cvta.to.shared.u64 t, %1; cvt.u32.u64 %0, t; }"
        : "=r"(a) : "l"(p));
    return a;
}
__device__ __forceinline__ void cp16(uint32_t saddr, const void* g) {
    asm volatile("cp.async.cg.shared.global [%0], [%1], 16;" :: "r"(saddr), "l"(g));
}
__device__ __forceinline__ void ldm_x4(uint32_t* r, uint32_t addr) {
    asm volatile("ldmatrix.sync.aligned.m8n8.x4.shared.b16 {%0,%1,%2,%3}, [%4];"
        : "=r"(r[0]), "=r"(r[1]), "=r"(r[2]), "=r"(r[3]) : "r"(addr));
}
__device__ __forceinline__ void ldm_x4_t(uint32_t* r, uint32_t addr) {
    asm volatile("ldmatrix.sync.aligned.m8n8.x4.trans.shared.b16 {%0,%1,%2,%3}, [%4];"
        : "=r"(r[0]), "=r"(r[1]), "=r"(r[2]), "=r"(r[3]) : "r"(addr));
}
__device__ __forceinline__ void mma16816(float* c, const uint32_t* a, const uint32_t* b) {
    asm volatile("mma.sync.aligned.m16n8k16.row.col.f32.bf16.bf16.f32 "
        "{%0,%1,%2,%3}, {%4,%5,%6,%7}, {%8,%9}, {%0,%1,%2,%3};"
        : "+f"(c[0]), "+f"(c[1]), "+f"(c[2]), "+f"(c[3])
        : "r"(a[0]), "r"(a[1]), "r"(a[2]), "r"(a[3]), "r"(b[0]), "r"(b[1]));
}
__device__ __forceinline__ void mma16816h(float* c, const uint32_t* a, const uint32_t* b) {
    asm volatile("mma.sync.aligned.m16n8k16.row.col.f32.f16.f16.f32 "
        "{%0,%1,%2,%3}, {%4,%5,%6,%7}, {%8,%9}, {%0,%1,%2,%3};"
        : "+f"(c[0]), "+f"(c[1]), "+f"(c[2]), "+f"(c[3])
        : "r"(a[0]), "r"(a[1]), "r"(a[2]), "r"(a[3]), "r"(b[0]), "r"(b[1]));
}
__device__ __forceinline__ uint32_t cvt_h2(float hi, float lo) {
    uint32_t d;
    asm("cvt.rn.f16x2.f32 %0, %1, %2;" : "=r"(d) : "f"(hi), "f"(lo));
    return d;
}
__device__ __forceinline__ uint32_t h2exp2(uint32_t x) {
    uint32_t d;
    asm("ex2.approx.f16x2 %0, %1;" : "=r"(d) : "r"(x));
    return d;
}
// bf16x3 element write: activation layout [hi | lo | hi], row stride 3K
__device__ __forceinline__ void write_a3_pair(__nv_bfloat16* rowp, int c, int K,
                                              float x, float y) {
    __nv_bfloat162 hi; hi.x = __float2bfloat16(x); hi.y = __float2bfloat16(y);
    __nv_bfloat162 lo;
    lo.x = __float2bfloat16(x - __bfloat162float(hi.x));
    lo.y = __float2bfloat16(y - __bfloat162float(hi.y));
    *(__nv_bfloat162*)(rowp + c)         = hi;
    *(__nv_bfloat162*)(rowp + c + K)     = lo;
    *(__nv_bfloat162*)(rowp + c + 2*K)   = hi;
}

// ---------------- weight converts ---------------------------------------------
__global__ void splitw_kernel(const float* __restrict__ X,
                              __nv_bfloat16* __restrict__ Y,
                              int K, int total)
{
    int i = blockIdx.x * 256 + threadIdx.x;
    if (i >= total) return;
    int r = i / K;
    int c = i - r * K;
    float x = X[i];
    __nv_bfloat16 hb = __float2bfloat16(x);
    float h = __bfloat162float(hb);
    __nv_bfloat16 lb = __float2bfloat16(x - h);
    size_t base = (size_t)r * (3 * K) + c;
    Y[base] = hb;
    Y[base + K] = hb;
    Y[base + 2*K] = lb;
}
__global__ void cvth_kernel(const float* __restrict__ X, __half* __restrict__ Y, int total)
{
    int i = blockIdx.x * 256 + threadIdx.x;
    if (i < total) Y[i] = __float2half(X[i]);
}

// ---------------- shared GEMM config (128x128, 4-stage) ------------------------
#define PADK 40
#define STAGES 4
#define AB_BYTES (128*PADK*2)               // 10240
#define STAGE_BYTES (2*AB_BYTES)            // 20480
#define BG_SMEM (STAGES*STAGE_BYTES)        // 81920

// ---------------- bf16x3 tensor-core GEMM (R6 config) --------------------------
// MODE 0: C = acc; MODE 2: C = acc + resid
template<int MODE>
__global__ __launch_bounds__(256) void bgemm_kernel(
    const __nv_bfloat16* __restrict__ A3, const __nv_bfloat16* __restrict__ W3,
    const float* __restrict__ resid, float* __restrict__ C,
    int Ndim, int K3)
{
    extern __shared__ char dynsmem[];
    const uint32_t base = smem_u32(dynsmem);

    const int tid = threadIdx.x;
    const int wid = tid >> 5, lid = tid & 31;
    const int wm = wid >> 1, wn = wid & 1;
    const int m0 = blockIdx.y * 128, n0 = blockIdx.x * 128;

    const __nv_bfloat16* Ag = A3 + (size_t)m0 * K3;
    const __nv_bfloat16* Wg = W3 + (size_t)n0 * K3;
    const int ntiles = K3 >> 5;

    const int ldr0 = tid >> 2, ldc0 = (tid & 3) * 8;
    const int ldr1 = (tid + 256) >> 2;
    const uint32_t so0 = (uint32_t)(ldr0*PADK + ldc0) * 2;
    const uint32_t so1 = (uint32_t)(ldr1*PADK + ldc0) * 2;

    float acc[2][8][4];
    #pragma unroll
    for (int i = 0; i < 2; i++)
        #pragma unroll
        for (int j = 0; j < 8; j++)
            #pragma unroll
            for (int x = 0; x < 4; x++) acc[i][j][x] = 0.f;

    const int aRowOff0 = (wm*32 + (lid & 15)) * PADK + (lid >> 4) * 8;
    const int aRowOff1 = aRowOff0 + 16 * PADK;
    const int bRowBase = (wn*64 + ((lid >> 4) & 1) * 8 + (lid & 7)) * PADK
                       + ((lid >> 3) & 1) * 8;

    #pragma unroll
    for (int t = 0; t < STAGES - 1; t++) {
        uint32_t sb = base + (uint32_t)t * STAGE_BYTES;
        const __nv_bfloat16* Agt = Ag + (size_t)t * 32;
        const __nv_bfloat16* Wgt = Wg + (size_t)t * 32;
        cp16(sb + so0,            Agt + (size_t)ldr0*K3 + ldc0);
        cp16(sb + AB_BYTES + so0, Wgt + (size_t)ldr0*K3 + ldc0);
        cp16(sb + so1,            Agt + (size_t)ldr1*K3 + ldc0);
        cp16(sb + AB_BYTES + so1, Wgt + (size_t)ldr1*K3 + ldc0);
        asm volatile("cp.async.commit_group;");
    }

    for (int t = 0; t < ntiles; t++) {
        asm volatile("cp.async.wait_group %0;" :: "n"(STAGES - 2));
        __syncthreads();

        if (t + STAGES - 1 < ntiles) {
            int tp = t + STAGES - 1;
            uint32_t sb = base + (uint32_t)(tp & (STAGES-1)) * STAGE_BYTES;
            const __nv_bfloat16* Agt = Ag + (size_t)tp * 32;
            const __nv_bfloat16* Wgt = Wg + (size_t)tp * 32;
            cp16(sb + so0,            Agt + (size_t)ldr0*K3 + ldc0);
            cp16(sb + AB_BYTES + so0, Wgt + (size_t)ldr0*K3 + ldc0);
            cp16(sb + so1,            Agt + (size_t)ldr1*K3 + ldc0);
            cp16(sb + AB_BYTES + so1, Wgt + (size_t)ldr1*K3 + ldc0);
        }
        asm volatile("cp.async.commit_group;");

        uint32_t aS = base + (uint32_t)(t & (STAGES-1)) * STAGE_BYTES;
        uint32_t bS = aS + AB_BYTES;

        #pragma unroll
        for (int ks = 0; ks < 2; ks++) {
            uint32_t afr[2][4];
            ldm_x4(afr[0], aS + (uint32_t)(aRowOff0 + ks*16) * 2);
            ldm_x4(afr[1], aS + (uint32_t)(aRowOff1 + ks*16) * 2);
            uint32_t bfr[4][4];
            #pragma unroll
            for (int np = 0; np < 4; np++)
                ldm_x4(bfr[np], bS + (uint32_t)(bRowBase + np*16*PADK + ks*16) * 2);
            #pragma unroll
            for (int mt = 0; mt < 2; mt++)
                #pragma unroll
                for (int np = 0; np < 4; np++) {
                    mma16816(acc[mt][2*np],     afr[mt], &bfr[np][0]);
                    mma16816(acc[mt][2*np + 1], afr[mt], &bfr[np][2]);
                }
        }
    }

    #pragma unroll
    for (int mt = 0; mt < 2; mt++) {
        int rbase = m0 + wm*32 + mt*16 + (lid >> 2);
        #pragma unroll
        for (int nt = 0; nt < 8; nt++) {
            int c = n0 + wn*64 + nt*8 + (lid & 3)*2;
            #pragma unroll
            for (int half = 0; half < 2; half++) {
                int n = rbase + half*8;
                float v0 = acc[mt][nt][2*half + 0];
                float v1 = acc[mt][nt][2*half + 1];
                float* cr = C + (size_t)n * Ndim + c;
                if (MODE == 2) {
                    const float2 rv = *(const float2*)(resid + (size_t)n * Ndim + c);
                    v0 += rv.x; v1 += rv.y;
                }
                float2 o; o.x = v0; o.y = v1;
                *(float2*)cr = o;
            }
        }
    }
}

// ---------------- f16 QKV GEMM (K=1024), epilogue -> f16 q/k/v -----------------
__global__ __launch_bounds__(256) void hgemm_qkv_kernel(
    const __half* __restrict__ Ah, const __half* __restrict__ Wh,
    const float* __restrict__ bias,
    __half* __restrict__ qout, __half* __restrict__ kout, __half* __restrict__ vout)
{
    extern __shared__ char dynsmem[];
    const uint32_t base = smem_u32(dynsmem);

    const int tid = threadIdx.x;
    const int wid = tid >> 5, lid = tid & 31;
    const int wm = wid >> 1, wn = wid & 1;
    const int m0 = blockIdx.y * 128, n0 = blockIdx.x * 128;
    const int K3 = DD;

    const __half* Ag = Ah + (size_t)m0 * K3;
    const __half* Wg = Wh + (size_t)n0 * K3;
    const int ntiles = K3 >> 5;

    const int ldr0 = tid >> 2, ldc0 = (tid & 3) * 8;
    const int ldr1 = (tid + 256) >> 2;
    const uint32_t so0 = (uint32_t)(ldr0*PADK + ldc0) * 2;
    const uint32_t so1 = (uint32_t)(ldr1*PADK + ldc0) * 2;

    float acc[2][8][4];
    #pragma unroll
    for (int i = 0; i < 2; i++)
        #pragma unroll
        for (int j = 0; j < 8; j++)
            #pragma unroll
            for (int x = 0; x < 4; x++) acc[i][j][x] = 0.f;

    const int aRowOff0 = (wm*32 + (lid & 15)) * PADK + (lid >> 4) * 8;
    const int aRowOff1 = aRowOff0 + 16 * PADK;
    const int bRowBase = (wn*64 + ((lid >> 4) & 1) * 8 + (lid & 7)) * PADK
                       + ((lid >> 3) & 1) * 8;

    #pragma unroll
    for (int t = 0; t < STAGES - 1; t++) {
        uint32_t sb = base + (uint32_t)t * STAGE_BYTES;
        const __half* Agt = Ag + (size_t)t * 32;
        const __half* Wgt = Wg + (size_t)t * 32;
        cp16(sb + so0,            Agt + (size_t)ldr0*K3 + ldc0);
        cp16(sb + AB_BYTES + so0, Wgt + (size_t)ldr0*K3 + ldc0);
        cp16(sb + so1,            Agt + (size_t)ldr1*K3 + ldc0);
        cp16(sb + AB_BYTES + so1, Wgt + (size_t)ldr1*K3 + ldc0);
        asm volatile("cp.async.commit_group;");
    }

    for (int t = 0; t < ntiles; t++) {
        asm volatile("cp.async.wait_group %0;" :: "n"(STAGES - 2));
        __syncthreads();

        if (t + STAGES - 1 < ntiles) {
            int tp = t + STAGES - 1;
            uint32_t sb = base + (uint32_t)(tp & (STAGES-1)) * STAGE_BYTES;
            const __half* Agt = Ag + (size_t)tp * 32;
            const __half* Wgt = Wg + (size_t)tp * 32;
            cp16(sb + so0,            Agt + (size_t)ldr0*K3 + ldc0);
            cp16(sb + AB_BYTES + so0, Wgt + (size_t)ldr0*K3 + ldc0);
            cp16(sb + so1,            Agt + (size_t)ldr1*K3 + ldc0);
            cp16(sb + AB_BYTES + so1, Wgt + (size_t)ldr1*K3 + ldc0);
        }
        asm volatile("cp.async.commit_group;");

        uint32_t aS = base + (uint32_t)(t & (STAGES-1)) * STAGE_BYTES;
        uint32_t bS = aS + AB_BYTES;

        #pragma unroll
        for (int ks = 0; ks < 2; ks++) {
            uint32_t afr[2][4];
            ldm_x4(afr[0], aS + (uint32_t)(aRowOff0 + ks*16) * 2);
            ldm_x4(afr[1], aS + (uint32_t)(aRowOff1 + ks*16) * 2);
            uint32_t bfr[4][4];
            #pragma unroll
            for (int np = 0; np < 4; np++)
                ldm_x4(bfr[np], bS + (uint32_t)(bRowBase + np*16*PADK + ks*16) * 2);
            #pragma unroll
            for (int mt = 0; mt < 2; mt++)
                #pragma unroll
                for (int np = 0; np < 4; np++) {
                    mma16816h(acc[mt][2*np],     afr[mt], &bfr[np][0]);
                    mma16816h(acc[mt][2*np + 1], afr[mt], &bfr[np][2]);
                }
        }
    }

    #pragma unroll
    for (int mt = 0; mt < 2; mt++) {
        int rbase = m0 + wm*32 + mt*16 + (lid >> 2);
        #pragma unroll
        for (int nt = 0; nt < 8; nt++) {
            int c = n0 + wn*64 + nt*8 + (lid & 3)*2;
            float2 bv = *(const float2*)(bias + c);
            int which = c >> 10, rem = c & 1023;
            int hh = rem >> 6, d0 = rem & 63;
            __half* dstbase = (which == 0) ? qout : (which == 1) ? kout : vout;
            #pragma unroll
            for (int half = 0; half < 2; half++) {
                int n = rbase + half*8;
                int b = n >> 11, m = n & 2047;
                float v0 = acc[mt][nt][2*half + 0] + bv.x;
                float v1 = acc[mt][nt][2*half + 1] + bv.y;
                __half2 hv; hv.x = __float2half(v0); hv.y = __float2half(v1);
                *(__half2*)(dstbase + ((size_t)(((b << 4) + hh) * MM + m)) * DH + d0) = hv;
            }
        }
    }
}

// ---------------- LayerNorm: OUT3=0 -> f16 single; OUT3=1 -> bf16x3 ------------
__inline__ __device__ float warpsum(float v) {
    #pragma unroll
    for (int o = 16; o; o >>= 1) v += __shfl_xor_sync(0xffffffff, v, o);
    return v;
}

template<int OUT3>
__global__ __launch_bounds__(256) void ln_kernel(
    const float* __restrict__ x, const float* __restrict__ w,
    const float* __restrict__ b, __nv_bfloat16* __restrict__ a3,
    __half* __restrict__ ah)
{
    __shared__ float red[2][8];
    int row = blockIdx.x;
    const float4* xr = (const float4*)(x + (size_t)row * DD);
    float4 v = xr[threadIdx.x];
    float s  = v.x + v.y + v.z + v.w;
    float ss = v.x*v.x + v.y*v.y + v.z*v.z + v.w*v.w;
    s = warpsum(s); ss = warpsum(ss);
    int wid = threadIdx.x >> 5, lid = threadIdx.x & 31;
    if (lid == 0) { red[0][wid] = s; red[1][wid] = ss; }
    __syncthreads();
    if (wid == 0) {
        float a = (lid < 8) ? red[0][lid] : 0.f;
        float c = (lid < 8) ? red[1][lid] : 0.f;
        a = warpsum(a); c = warpsum(c);
        if (lid == 0) { red[0][0] = a; red[1][0] = c; }
    }
    __syncthreads();
    float mean = red[0][0] * (1.0f/DD);
    float var  = red[1][0] * (1.0f/DD) - mean*mean;
    float rstd = rsqrtf(var + 1e-5f);
    float4 wv = ((const float4*)w)[threadIdx.x];
    float4 bv = ((const float4*)b)[threadIdx.x];
    float o0 = (v.x - mean)*rstd*wv.x + bv.x;
    float o1 = (v.y - mean)*rstd*wv.y + bv.y;
    float o2 = (v.z - mean)*rstd*wv.z + bv.z;
    float o3 = (v.w - mean)*rstd*wv.w + bv.w;
    int c = threadIdx.x * 4;
    if (OUT3) {
        __nv_bfloat16* rowp = a3 + (size_t)row * (3*DD);
        write_a3_pair(rowp, c,     DD, o0, o1);
        write_a3_pair(rowp, c + 2, DD, o2, o3);
    } else {
        __half* rowp = ah + (size_t)row * DD;
        __half2 h0; h0.x = __float2half(o0); h0.y = __float2half(o1);
        __half2 h1; h1.x = __float2half(o2); h1.y = __float2half(o3);
        *(__half2*)(rowp + c)     = h0;
        *(__half2*)(rowp + c + 2) = h1;
    }
}

// ---------------- RoPE table + in-place f16 apply ------------------------------
__global__ void ropetab_kernel(float2* __restrict__ tab)
{
    int gid = blockIdx.x * 256 + threadIdx.x;     // over MM*32
    int i = gid & 31;
    int m = gid >> 5;
    float invf = (float)exp2(-(double)i * (13.287712379549449 / 32.0));
    float angle = (float)m * invf;
    float sv, cv;
    sincosf(angle, &sv, &cv);
    tab[gid] = make_float2(cv, sv);
}

#define QSCALE 0.18033688011112042f   // 0.125 * log2(e)
__global__ void rope_kernel(__half* __restrict__ q2, __half* __restrict__ k2,
                            const float2* __restrict__ tab)
{
    int gid = blockIdx.x * blockDim.x + threadIdx.x;   // over B*H*M*32
    int i = gid & 31;
    int r = gid >> 5;
    int m = r & (MM - 1);
    float2 cs = tab[(m << 5) | i];
    float cv = cs.x, sv = cs.y;
    size_t base = (size_t)r * DH + i;
    float q1 = __half2float(q2[base]), qq2 = __half2float(q2[base + 32]);
    q2[base]      = __float2half((q1 * cv - qq2 * sv) * QSCALE);
    q2[base + 32] = __float2half((q1 * sv + qq2 * cv) * QSCALE);
    float k1 = __half2float(k2[base]), kk2 = __half2float(k2[base + 32]);
    k2[base]      = __float2half(k1 * cv - kk2 * sv);
    k2[base + 32] = __float2half(k1 * sv + kk2 * cv);
}

// ---------------- Flash attention: f16 mma.sync, epilogue -> bf16x3 -----------
#define ASTR 72
__global__ __launch_bounds__(128) void attn_kernel(
    const __half* __restrict__ Q2, const __half* __restrict__ K2,
    const __half* __restrict__ V2, const int* __restrict__ amask,
    __nv_bfloat16* __restrict__ a3)
{
    __shared__ __half Qs[64][ASTR];
    __shared__ __half Ks[2][64][ASTR];
    __shared__ __half Vs[2][64][ASTR];
    __shared__ __half2 Ms[2][32];

    const int tid = threadIdx.x, wid = tid >> 5, lid = tid & 31;
    const int bh = blockIdx.y;
    const int b = bh >> 4, h = bh & 15;
    const int q0 = blockIdx.x * 64;

    uint32_t qB = smem_u32(Qs);
    uint32_t kB = smem_u32(Ks);
    uint32_t vB = smem_u32(Vs);

    const __half* Qg = Q2 + ((size_t)bh * MM + q0) * DH;
    const __half* Kg = K2 + (size_t)bh * MM * DH;
    const __half* Vg = V2 + (size_t)bh * MM * DH;

    #pragma unroll
    for (int j = 0; j < 4; j++) {
        int idx = tid + j * 128;
        int row = idx >> 3, ch = (idx & 7) * 8;
        cp16(qB + (row*ASTR + ch)*2, Qg + row*DH + ch);
        cp16(kB + (row*ASTR + ch)*2, Kg + row*DH + ch);
        cp16(vB + (row*ASTR + ch)*2, Vg + row*DH + ch);
    }
    if (tid < 32) {
        int ka = amask[b*MM + 2*tid], kb2 = amask[b*MM + 2*tid + 1];
        Ms[0][tid] = __halves2half2(__int2half_rn(ka ? 1 : 0), __int2half_rn(kb2 ? 1 : 0));
    }
    asm volatile("cp.async.commit_group;");

    float o[8][4];
    #pragma unroll
    for (int f = 0; f < 8; f++)
        #pragma unroll
        for (int j = 0; j < 4; j++) o[f][j] = 0.f;
    float lr0 = 0.f, lr1 = 0.f;

    const uint32_t aAddrBase = qB + ((uint32_t)(wid*16 + (lid & 15)) * ASTR + (lid >> 4) * 8) * 2;
    const uint32_t bRowOff = ((uint32_t)(((lid >> 4) & 1) * 8 + (lid & 7)) * ASTR + ((lid >> 3) & 1) * 8) * 2;
    const uint32_t vRowOff = ((uint32_t)(lid & 15) * ASTR + (lid >> 4) * 8) * 2;

    for (int kt = 0; kt < 32; kt++) {
        int s = kt & 1;
        if (kt + 1 < 32) {
            int s2 = s ^ 1;
            const __half* Kn = Kg + (size_t)(kt + 1) * 64 * DH;
            const __half* Vn = Vg + (size_t)(kt + 1) * 64 * DH;
            #pragma unroll
            for (int j = 0; j < 4; j++) {
                int idx = tid + j * 128;
                int row = idx >> 3, ch = (idx & 7) * 8;
                cp16(kB + (s2*64*ASTR + row*ASTR + ch)*2, Kn + row*DH + ch);
                cp16(vB + (s2*64*ASTR + row*ASTR + ch)*2, Vn + row*DH + ch);
            }
            if (tid < 32) {
                int kbase = b*MM + (kt + 1)*64;
                int ka = amask[kbase + 2*tid], kb2 = amask[kbase + 2*tid + 1];
                Ms[s2][tid] = __halves2half2(__int2half_rn(ka ? 1 : 0), __int2half_rn(kb2 ? 1 : 0));
            }
            asm volatile("cp.async.commit_group;");
            asm volatile("cp.async.wait_group 1;");
        } else {
            asm volatile("cp.async.wait_group 0;");
        }
        __syncthreads();

        uint32_t kS = kB + (uint32_t)s * 64 * ASTR * 2;
        uint32_t vS = vB + (uint32_t)s * 64 * ASTR * 2;

        float sacc[8][4];
        #pragma unroll
        for (int f = 0; f < 8; f++)
            #pragma unroll
            for (int j = 0; j < 4; j++) sacc[f][j] = 0.f;

        #pragma unroll
        for (int kk = 0; kk < 4; kk++) {
            uint32_t aq[4];
            ldm_x4(aq, aAddrBase + (uint32_t)(kk * 16) * 2);
            #pragma unroll
            for (int np = 0; np < 4; np++) {
                uint32_t bk[4];
                ldm_x4(bk, kS + (uint32_t)(np * 16) * ASTR * 2 + bRowOff + (uint32_t)(kk * 16) * 2);
                mma16816h(sacc[2*np],     aq, &bk[0]);
                mma16816h(sacc[2*np + 1], aq, &bk[2]);
            }
        }

        uint32_t p0[8], p1[8];
        __half2 l2a = __halves2half2(__float2half(0.f), __float2half(0.f));
        __half2 l2b = l2a;
        #pragma unroll
        for (int f = 0; f < 8; f++) {
            __half2 m2 = Ms[s][4*f + (lid & 3)];
            uint32_t e0u = h2exp2(cvt_h2(sacc[f][1], sacc[f][0]));
            uint32_t e1u = h2exp2(cvt_h2(sacc[f][3], sacc[f][2]));
            __half2 e0 = __hmul2(*reinterpret_cast<__half2*>(&e0u), m2);
            __half2 e1 = __hmul2(*reinterpret_cast<__half2*>(&e1u), m2);
            p0[f] = *(uint32_t*)&e0;
            p1[f] = *(uint32_t*)&e1;
            l2a = __hadd2(l2a, e0);
            l2b = __hadd2(l2b, e1);
        }
        lr0 += __low2float(l2a) + __high2float(l2a);
        lr1 += __low2float(l2b) + __high2float(l2b);

        #pragma unroll
        for (int kk = 0; kk < 4; kk++) {
            uint32_t A[4] = { p0[2*kk], p1[2*kk], p0[2*kk + 1], p1[2*kk + 1] };
            #pragma unroll
            for (int np = 0; np < 4; np++) {
                uint32_t bv[4];
                ldm_x4_t(bv, vS + (uint32_t)(kk * 16) * ASTR * 2 + vRowOff + (uint32_t)(np * 16) * 2);
                mma16816h(o[2*np],     A, &bv[0]);
                mma16816h(o[2*np + 1], A, &bv[2]);
            }
        }
        __syncthreads();
    }

    lr0 += __shfl_xor_sync(0xffffffff, lr0, 1);
    lr0 += __shfl_xor_sync(0xffffffff, lr0, 2);
    lr1 += __shfl_xor_sync(0xffffffff, lr1, 1);
    lr1 += __shfl_xor_sync(0xffffffff, lr1, 2);
    float inv0 = 1.0f / lr0, inv1 = 1.0f / lr1;

    int gm0 = q0 + wid*16 + (lid >> 2);
    int gm1 = gm0 + 8;
    __nv_bfloat16* r0p = a3 + (size_t)(b * MM + gm0) * (3*DD) + h * DH;
    __nv_bfloat16* r1p = a3 + (size_t)(b * MM + gm1) * (3*DD) + h * DH;
    #pragma unroll
    for (int f = 0; f < 8; f++) {
        int c = 8*f + (lid & 3)*2;
        write_a3_pair(r0p, c, DD, o[f][0]*inv0, o[f][1]*inv0);
        write_a3_pair(r1p, c, DD, o[f][2]*inv1, o[f][3]*inv1);
    }
}

// ---------------- GeGLU -> bf16x3 directly ------------------------------------
__global__ void geglu_kernel(const float* __restrict__ g, __nv_bfloat16* __restrict__ a3)
{
    int n = blockIdx.x;
    const float* gr = g + (size_t)n * WI_N;
    __nv_bfloat16* rowp = a3 + (size_t)n * (3*FF);
    for (int f = threadIdx.x * 2; f < FF; f += blockDim.x * 2) {
        float2 x2 = *(const float2*)(gr + f);
        float2 gt = *(const float2*)(gr + f + FF);
        float v0 = 0.5f * x2.x * (1.0f + erff(x2.x * 0.7071067811865476f)) * gt.x;
        float v1 = 0.5f * x2.y * (1.0f + erff(x2.y * 0.7071067811865476f)) * gt.y;
        write_a3_pair(rowp, f, FF, v0, v1);
    }
}

// ---------------- launch ------------------------------------------------------
extern "C" void kernel_launch(void* const* d_in, const int* in_sizes, int n_in,
                              void* d_out, int out_size)
{
    const float* hs     = (const float*)d_in[0];
    const int*   amask  = (const int*)  d_in[1];
    const float* ln1w   = (const float*)d_in[2];
    const float* ln1b   = (const float*)d_in[3];
    const float* wqkv_w = (const float*)d_in[4];
    const float* wqkv_b = (const float*)d_in[5];
    const float* wo_w   = (const float*)d_in[6];
    const float* ln2w   = (const float*)d_in[7];
    const float* ln2b   = (const float*)d_in[8];
    const float* wi_w   = (const float*)d_in[9];
    const float* womlp  = (const float*)d_in[10];
    float* out = (float*)d_out;

    float *xres, *gg;
    float2* rtab;
    __nv_bfloat16 *a3, *w3;
    __half *xh, *wh, *q2, *k2, *v2;
    cudaGetSymbolAddress((void**)&xres, g_xres);
    cudaGetSymbolAddress((void**)&gg,   g_g);
    cudaGetSymbolAddress((void**)&rtab, g_rope);
    cudaGetSymbolAddress((void**)&a3,   g_a3);
    cudaGetSymbolAddress((void**)&w3,   g_w3);
    cudaGetSymbolAddress((void**)&xh,   g_xh);
    cudaGetSymbolAddress((void**)&wh,   g_wh);
    cudaGetSymbolAddress((void**)&q2,   g_q2);
    cudaGetSymbolAddress((void**)&k2,   g_k2);
    cudaGetSymbolAddress((void**)&v2,   g_v2);

    cudaFuncSetAttribute(bgemm_kernel<0>, cudaFuncAttributeMaxDynamicSharedMemorySize, BG_SMEM);
    cudaFuncSetAttribute(bgemm_kernel<2>, cudaFuncAttributeMaxDynamicSharedMemorySize, BG_SMEM);
    cudaFuncSetAttribute(hgemm_qkv_kernel, cudaFuncAttributeMaxDynamicSharedMemorySize, BG_SMEM);

    // 0. RoPE table
    ropetab_kernel<<<(MM*32)/256, 256>>>(rtab);

    // 1. LN1 -> xh (f16)
    ln_kernel<0><<<NTOK, 256>>>(hs, ln1w, ln1b, nullptr, xh);

    // 2. QKV gemm (pure f16, K=1024) -> q2/k2/v2 f16
    cvth_kernel<<<(QKV_N*DD + 255)/256, 256>>>(wqkv_w, wh, QKV_N*DD);
    hgemm_qkv_kernel<<<dim3(QKV_N/128, NTOK/128), 256, BG_SMEM>>>(
        xh, wh, wqkv_b, q2, k2, v2);

    // 3. RoPE in-place on q2,k2 (q scaled to log2 domain)
    rope_kernel<<<(BB*HH*MM*32)/256, 256>>>(q2, k2, rtab);

    // 4. Flash attention -> a3 (bf16x3 of attention output)
    attn_kernel<<<dim3(MM/64, BB*HH), 128>>>(q2, k2, v2, amask, a3);

    // 5. O projection + residual -> xres
    {
        int totw = DD * DD;
        splitw_kernel<<<(totw + 255)/256, 256>>>(wo_w, w3, DD, totw);
        bgemm_kernel<2><<<dim3(DD/128, NTOK/128), 256, BG_SMEM>>>(
            a3, w3, hs, xres, DD, 3*DD);
    }

    // 6. LN2 -> a3 (bf16x3)
    ln_kernel<1><<<NTOK, 256>>>(xres, ln2w, ln2b, a3, nullptr);

    // 7. Wi gemm -> gg fp32
    {
        int totw = WI_N * DD;
        splitw_kernel<<<(totw + 255)/256, 256>>>(wi_w, w3, DD, totw);
        bgemm_kernel<0><<<dim3(WI_N/128, NTOK/128), 256, BG_SMEM>>>(
            a3, w3, nullptr, gg, WI_N, 3*DD);
    }

    // 8. GeGLU -> a3 (K=FF layout)
    geglu_kernel<<<NTOK, 256>>>(gg, a3);

    // 9. Wo_mlp gemm + residual -> out
    {
        int totw = DD * FF;
        splitw_kernel<<<(totw + 255)/256, 256>>>(womlp, w3, FF, totw);
        bgemm_kernel<2><<<dim3(DD/128, NTOK/128), 256, BG_SMEM>>>(
            a3, w3, xres, out, DD, 3*FF);
    }
}

// round 12
// speedup vs baseline: 2.4152x; 1.8899x over previous
#include <cuda_runtime.h>
#include <cuda_bf16.h>
#include <cuda_fp16.h>
#include <math.h>
#include <stdint.h>

// Problem constants
#define BB 2
#define MM 2048
#define DD 1024
#define HH 16
#define DH 64
#define FF 2624
#define NTOK (BB*MM)           // 4096
#define QKV_N (3*DD)           // 3072
#define WI_N (2*FF)            // 5248

// ---------------- scratch (device globals; no allocation allowed) -------------
__device__ float g_xres[NTOK*DD];
__device__ float2 g_rope[MM*32];
// f16 buffers
__device__ __align__(128) __half g_xh [(size_t)NTOK*DD];     // LN1/attn/LN2 out (sequential reuse)
__device__ __align__(128) __half g_wh [(size_t)WI_N*DD];     // current weight, f16
__device__ __align__(128) __half g_gg [(size_t)NTOK*WI_N];   // wi out f16
__device__ __align__(128) __half g_act[(size_t)NTOK*FF];     // geglu out f16
__device__ __align__(128) __half g_q2[(size_t)BB*HH*MM*DH];
__device__ __align__(128) __half g_k2[(size_t)BB*HH*MM*DH];
__device__ __align__(128) __half g_v2[(size_t)BB*HH*MM*DH];

// ---------------- PTX helpers (base compute_80 features only) -----------------
__device__ __forceinline__ uint32_t smem_u32(const void* p) {
    uint32_t a;
    asm("{ .reg .u64 t; cvta.to.shared.u64 t, %1; cvt.u32.u64 %0, t; }"
        : "=r"(a) : "l"(p));
    return a;
}
__device__ __forceinline__ void cp16(uint32_t saddr, const void* g) {
    asm volatile("cp.async.cg.shared.global [%0], [%1], 16;" :: "r"(saddr), "l"(g));
}
__device__ __forceinline__ void ldm_x4(uint32_t* r, uint32_t addr) {
    asm volatile("ldmatrix.sync.aligned.m8n8.x4.shared.b16 {%0,%1,%2,%3}, [%4];"
        : "=r"(r[0]), "=r"(r[1]), "=r"(r[2]), "=r"(r[3]) : "r"(addr));
}
__device__ __forceinline__ void ldm_x4_t(uint32_t* r, uint32_t addr) {
    asm volatile("ldmatrix.sync.aligned.m8n8.x4.trans.shared.b16 {%0,%1,%2,%3}, [%4];"
        : "=r"(r[0]), "=r"(r[1]), "=r"(r[2]), "=r"(r[3]) : "r"(addr));
}
__device__ __forceinline__ void mma16816h(float* c, const uint32_t* a, const uint32_t* b) {
    asm volatile("mma.sync.aligned.m16n8k16.row.col.f32.f16.f16.f32 "
        "{%0,%1,%2,%3}, {%4,%5,%6,%7}, {%8,%9}, {%0,%1,%2,%3};"
        : "+f"(c[0]), "+f"(c[1]), "+f"(c[2]), "+f"(c[3])
        : "r"(a[0]), "r"(a[1]), "r"(a[2]), "r"(a[3]), "r"(b[0]), "r"(b[1]));
}
__device__ __forceinline__ uint32_t cvt_h2(float hi, float lo) {
    uint32_t d;
    asm("cvt.rn.f16x2.f32 %0, %1, %2;" : "=r"(d) : "f"(hi), "f"(lo));
    return d;
}
__device__ __forceinline__ uint32_t h2exp2(uint32_t x) {
    uint32_t d;
    asm("ex2.approx.f16x2 %0, %1;" : "=r"(d) : "r"(x));
    return d;
}

// ---------------- weight convert fp32 -> f16 -----------------------------------
__global__ void cvth_kernel(const float* __restrict__ X, __half* __restrict__ Y, int total)
{
    int i = blockIdx.x * 256 + threadIdx.x;
    if (i < total) Y[i] = __float2half(X[i]);
}

// ---------------- unified f16 GEMM (128x128, 4-stage cp.async) -----------------
// MODE 0: f16 C = acc              (Wi)
// MODE 1: QKV scatter + bias -> f16 q/k/v
// MODE 2: fp32 C = acc + fp32 resid (O-proj, Wo_mlp)
#define PADK 40
#define STAGES 4
#define AB_BYTES (128*PADK*2)               // 10240
#define STAGE_BYTES (2*AB_BYTES)            // 20480
#define BG_SMEM (STAGES*STAGE_BYTES)        // 81920

template<int MODE>
__global__ __launch_bounds__(256) void hgemm_kernel(
    const __half* __restrict__ Ah, const __half* __restrict__ Wh,
    const float* __restrict__ bias, const float* __restrict__ resid,
    float* __restrict__ Cf, __half* __restrict__ Chalf,
    __half* __restrict__ qout, __half* __restrict__ kout, __half* __restrict__ vout,
    int Ndim, int K3)
{
    extern __shared__ char dynsmem[];
    const uint32_t base = smem_u32(dynsmem);

    const int tid = threadIdx.x;
    const int wid = tid >> 5, lid = tid & 31;
    const int wm = wid >> 1, wn = wid & 1;
    const int m0 = blockIdx.y * 128, n0 = blockIdx.x * 128;

    const __half* Ag = Ah + (size_t)m0 * K3;
    const __half* Wg = Wh + (size_t)n0 * K3;
    const int ntiles = K3 >> 5;

    const int ldr0 = tid >> 2, ldc0 = (tid & 3) * 8;
    const int ldr1 = (tid + 256) >> 2;
    const uint32_t so0 = (uint32_t)(ldr0*PADK + ldc0) * 2;
    const uint32_t so1 = (uint32_t)(ldr1*PADK + ldc0) * 2;

    float acc[2][8][4];
    #pragma unroll
    for (int i = 0; i < 2; i++)
        #pragma unroll
        for (int j = 0; j < 8; j++)
            #pragma unroll
            for (int x = 0; x < 4; x++) acc[i][j][x] = 0.f;

    const int aRowOff0 = (wm*32 + (lid & 15)) * PADK + (lid >> 4) * 8;
    const int aRowOff1 = aRowOff0 + 16 * PADK;
    const int bRowBase = (wn*64 + ((lid >> 4) & 1) * 8 + (lid & 7)) * PADK
                       + ((lid >> 3) & 1) * 8;

    #pragma unroll
    for (int t = 0; t < STAGES - 1; t++) {
        uint32_t sb = base + (uint32_t)t * STAGE_BYTES;
        const __half* Agt = Ag + (size_t)t * 32;
        const __half* Wgt = Wg + (size_t)t * 32;
        cp16(sb + so0,            Agt + (size_t)ldr0*K3 + ldc0);
        cp16(sb + AB_BYTES + so0, Wgt + (size_t)ldr0*K3 + ldc0);
        cp16(sb + so1,            Agt + (size_t)ldr1*K3 + ldc0);
        cp16(sb + AB_BYTES + so1, Wgt + (size_t)ldr1*K3 + ldc0);
        asm volatile("cp.async.commit_group;");
    }

    for (int t = 0; t < ntiles; t++) {
        asm volatile("cp.async.wait_group %0;" :: "n"(STAGES - 2));
        __syncthreads();

        if (t + STAGES - 1 < ntiles) {
            int tp = t + STAGES - 1;
            uint32_t sb = base + (uint32_t)(tp & (STAGES-1)) * STAGE_BYTES;
            const __half* Agt = Ag + (size_t)tp * 32;
            const __half* Wgt = Wg + (size_t)tp * 32;
            cp16(sb + so0,            Agt + (size_t)ldr0*K3 + ldc0);
            cp16(sb + AB_BYTES + so0, Wgt + (size_t)ldr0*K3 + ldc0);
            cp16(sb + so1,            Agt + (size_t)ldr1*K3 + ldc0);
            cp16(sb + AB_BYTES + so1, Wgt + (size_t)ldr1*K3 + ldc0);
        }
        asm volatile("cp.async.commit_group;");

        uint32_t aS = base + (uint32_t)(t & (STAGES-1)) * STAGE_BYTES;
        uint32_t bS = aS + AB_BYTES;

        #pragma unroll
        for (int ks = 0; ks < 2; ks++) {
            uint32_t afr[2][4];
            ldm_x4(afr[0], aS + (uint32_t)(aRowOff0 + ks*16) * 2);
            ldm_x4(afr[1], aS + (uint32_t)(aRowOff1 + ks*16) * 2);
            uint32_t bfr[4][4];
            #pragma unroll
            for (int np = 0; np < 4; np++)
                ldm_x4(bfr[np], bS + (uint32_t)(bRowBase + np*16*PADK + ks*16) * 2);
            #pragma unroll
            for (int mt = 0; mt < 2; mt++)
                #pragma unroll
                for (int np = 0; np < 4; np++) {
                    mma16816h(acc[mt][2*np],     afr[mt], &bfr[np][0]);
                    mma16816h(acc[mt][2*np + 1], afr[mt], &bfr[np][2]);
                }
        }
    }

    #pragma unroll
    for (int mt = 0; mt < 2; mt++) {
        int rbase = m0 + wm*32 + mt*16 + (lid >> 2);
        #pragma unroll
        for (int nt = 0; nt < 8; nt++) {
            int c = n0 + wn*64 + nt*8 + (lid & 3)*2;
            #pragma unroll
            for (int half = 0; half < 2; half++) {
                int n = rbase + half*8;
                float v0 = acc[mt][nt][2*half + 0];
                float v1 = acc[mt][nt][2*half + 1];
                if (MODE == 1) {
                    float2 bv = *(const float2*)(bias + c);
                    v0 += bv.x; v1 += bv.y;
                    int b = n >> 11, m = n & 2047;
                    int which = c >> 10, rem = c & 1023;
                    int hh = rem >> 6, d0 = rem & 63;
                    __half* dst = ((which == 0) ? qout : (which == 1) ? kout : vout)
                               + ((size_t)(((b << 4) + hh) * MM + m)) * DH + d0;
                    __half2 hv; hv.x = __float2half(v0); hv.y = __float2half(v1);
                    *(__half2*)dst = hv;
                } else if (MODE == 0) {
                    __half2 hv; hv.x = __float2half(v0); hv.y = __float2half(v1);
                    *(__half2*)(Chalf + (size_t)n * Ndim + c) = hv;
                } else {
                    const float2 rv = *(const float2*)(resid + (size_t)n * Ndim + c);
                    float2 o; o.x = v0 + rv.x; o.y = v1 + rv.y;
                    *(float2*)(Cf + (size_t)n * Ndim + c) = o;
                }
            }
        }
    }
}

// ---------------- LayerNorm -> f16 ---------------------------------------------
__inline__ __device__ float warpsum(float v) {
    #pragma unroll
    for (int o = 16; o; o >>= 1) v += __shfl_xor_sync(0xffffffff, v, o);
    return v;
}

__global__ __launch_bounds__(256) void ln_kernel(
    const float* __restrict__ x, const float* __restrict__ w,
    const float* __restrict__ b, __half* __restrict__ ah)
{
    __shared__ float red[2][8];
    int row = blockIdx.x;
    const float4* xr = (const float4*)(x + (size_t)row * DD);
    float4 v = xr[threadIdx.x];
    float s  = v.x + v.y + v.z + v.w;
    float ss = v.x*v.x + v.y*v.y + v.z*v.z + v.w*v.w;
    s = warpsum(s); ss = warpsum(ss);
    int wid = threadIdx.x >> 5, lid = threadIdx.x & 31;
    if (lid == 0) { red[0][wid] = s; red[1][wid] = ss; }
    __syncthreads();
    if (wid == 0) {
        float a = (lid < 8) ? red[0][lid] : 0.f;
        float c = (lid < 8) ? red[1][lid] : 0.f;
        a = warpsum(a); c = warpsum(c);
        if (lid == 0) { red[0][0] = a; red[1][0] = c; }
    }
    __syncthreads();
    float mean = red[0][0] * (1.0f/DD);
    float var  = red[1][0] * (1.0f/DD) - mean*mean;
    float rstd = rsqrtf(var + 1e-5f);
    float4 wv = ((const float4*)w)[threadIdx.x];
    float4 bv = ((const float4*)b)[threadIdx.x];
    float o0 = (v.x - mean)*rstd*wv.x + bv.x;
    float o1 = (v.y - mean)*rstd*wv.y + bv.y;
    float o2 = (v.z - mean)*rstd*wv.z + bv.z;
    float o3 = (v.w - mean)*rstd*wv.w + bv.w;
    __half* rowp = ah + (size_t)row * DD;
    int c = threadIdx.x * 4;
    __half2 h0; h0.x = __float2half(o0); h0.y = __float2half(o1);
    __half2 h1; h1.x = __float2half(o2); h1.y = __float2half(o3);
    *(__half2*)(rowp + c)     = h0;
    *(__half2*)(rowp + c + 2) = h1;
}

// ---------------- RoPE table + in-place f16 apply ------------------------------
__global__ void ropetab_kernel(float2* __restrict__ tab)
{
    int gid = blockIdx.x * 256 + threadIdx.x;     // over MM*32
    int i = gid & 31;
    int m = gid >> 5;
    float invf = (float)exp2(-(double)i * (13.287712379549449 / 32.0));
    float angle = (float)m * invf;
    float sv, cv;
    sincosf(angle, &sv, &cv);
    tab[gid] = make_float2(cv, sv);
}

#define QSCALE 0.18033688011112042f   // 0.125 * log2(e)
__global__ void rope_kernel(__half* __restrict__ q2, __half* __restrict__ k2,
                            const float2* __restrict__ tab)
{
    int gid = blockIdx.x * blockDim.x + threadIdx.x;   // over B*H*M*32
    int i = gid & 31;
    int r = gid >> 5;
    int m = r & (MM - 1);
    float2 cs = tab[(m << 5) | i];
    float cv = cs.x, sv = cs.y;
    size_t base = (size_t)r * DH + i;
    float q1 = __half2float(q2[base]), qq2 = __half2float(q2[base + 32]);
    q2[base]      = __float2half((q1 * cv - qq2 * sv) * QSCALE);
    q2[base + 32] = __float2half((q1 * sv + qq2 * cv) * QSCALE);
    float k1 = __half2float(k2[base]), kk2 = __half2float(k2[base + 32]);
    k2[base]      = __float2half(k1 * cv - kk2 * sv);
    k2[base + 32] = __float2half(k1 * sv + kk2 * cv);
}

// ---------------- Flash attention: f16 mma.sync, epilogue -> f16 ---------------
#define ASTR 72
__global__ __launch_bounds__(128) void attn_kernel(
    const __half* __restrict__ Q2, const __half* __restrict__ K2,
    const __half* __restrict__ V2, const int* __restrict__ amask,
    __half* __restrict__ aout)
{
    __shared__ __half Qs[64][ASTR];
    __shared__ __half Ks[2][64][ASTR];
    __shared__ __half Vs[2][64][ASTR];
    __shared__ __half2 Ms[2][32];

    const int tid = threadIdx.x, wid = tid >> 5, lid = tid & 31;
    const int bh = blockIdx.y;
    const int b = bh >> 4, h = bh & 15;
    const int q0 = blockIdx.x * 64;

    uint32_t qB = smem_u32(Qs);
    uint32_t kB = smem_u32(Ks);
    uint32_t vB = smem_u32(Vs);

    const __half* Qg = Q2 + ((size_t)bh * MM + q0) * DH;
    const __half* Kg = K2 + (size_t)bh * MM * DH;
    const __half* Vg = V2 + (size_t)bh * MM * DH;

    #pragma unroll
    for (int j = 0; j < 4; j++) {
        int idx = tid + j * 128;
        int row = idx >> 3, ch = (idx & 7) * 8;
        cp16(qB + (row*ASTR + ch)*2, Qg + row*DH + ch);
        cp16(kB + (row*ASTR + ch)*2, Kg + row*DH + ch);
        cp16(vB + (row*ASTR + ch)*2, Vg + row*DH + ch);
    }
    if (tid < 32) {
        int ka = amask[b*MM + 2*tid], kb2 = amask[b*MM + 2*tid + 1];
        Ms[0][tid] = __halves2half2(__int2half_rn(ka ? 1 : 0), __int2half_rn(kb2 ? 1 : 0));
    }
    asm volatile("cp.async.commit_group;");

    float o[8][4];
    #pragma unroll
    for (int f = 0; f < 8; f++)
        #pragma unroll
        for (int j = 0; j < 4; j++) o[f][j] = 0.f;
    float lr0 = 0.f, lr1 = 0.f;

    const uint32_t aAddrBase = qB + ((uint32_t)(wid*16 + (lid & 15)) * ASTR + (lid >> 4) * 8) * 2;
    const uint32_t bRowOff = ((uint32_t)(((lid >> 4) & 1) * 8 + (lid & 7)) * ASTR + ((lid >> 3) & 1) * 8) * 2;
    const uint32_t vRowOff = ((uint32_t)(lid & 15) * ASTR + (lid >> 4) * 8) * 2;

    for (int kt = 0; kt < 32; kt++) {
        int s = kt & 1;
        if (kt + 1 < 32) {
            int s2 = s ^ 1;
            const __half* Kn = Kg + (size_t)(kt + 1) * 64 * DH;
            const __half* Vn = Vg + (size_t)(kt + 1) * 64 * DH;
            #pragma unroll
            for (int j = 0; j < 4; j++) {
                int idx = tid + j * 128;
                int row = idx >> 3, ch = (idx & 7) * 8;
                cp16(kB + (s2*64*ASTR + row*ASTR + ch)*2, Kn + row*DH + ch);
                cp16(vB + (s2*64*ASTR + row*ASTR + ch)*2, Vn + row*DH + ch);
            }
            if (tid < 32) {
                int kbase = b*MM + (kt + 1)*64;
                int ka = amask[kbase + 2*tid], kb2 = amask[kbase + 2*tid + 1];
                Ms[s2][tid] = __halves2half2(__int2half_rn(ka ? 1 : 0), __int2half_rn(kb2 ? 1 : 0));
            }
            asm volatile("cp.async.commit_group;");
            asm volatile("cp.async.wait_group 1;");
        } else {
            asm volatile("cp.async.wait_group 0;");
        }
        __syncthreads();

        uint32_t kS = kB + (uint32_t)s * 64 * ASTR * 2;
        uint32_t vS = vB + (uint32_t)s * 64 * ASTR * 2;

        float sacc[8][4];
        #pragma unroll
        for (int f = 0; f < 8; f++)
            #pragma unroll
            for (int j = 0; j < 4; j++) sacc[f][j] = 0.f;

        #pragma unroll
        for (int kk = 0; kk < 4; kk++) {
            uint32_t aq[4];
            ldm_x4(aq, aAddrBase + (uint32_t)(kk * 16) * 2);
            #pragma unroll
            for (int np = 0; np < 4; np++) {
                uint32_t bk[4];
                ldm_x4(bk, kS + (uint32_t)(np * 16) * ASTR * 2 + bRowOff + (uint32_t)(kk * 16) * 2);
                mma16816h(sacc[2*np],     aq, &bk[0]);
                mma16816h(sacc[2*np + 1], aq, &bk[2]);
            }
        }

        uint32_t p0[8], p1[8];
        __half2 l2a = __halves2half2(__float2half(0.f), __float2half(0.f));
        __half2 l2b = l2a;
        #pragma unroll
        for (int f = 0; f < 8; f++) {
            __half2 m2 = Ms[s][4*f + (lid & 3)];
            uint32_t e0u = h2exp2(cvt_h2(sacc[f][1], sacc[f][0]));
            uint32_t e1u = h2exp2(cvt_h2(sacc[f][3], sacc[f][2]));
            __half2 e0 = __hmul2(*reinterpret_cast<__half2*>(&e0u), m2);
            __half2 e1 = __hmul2(*reinterpret_cast<__half2*>(&e1u), m2);
            p0[f] = *(uint32_t*)&e0;
            p1[f] = *(uint32_t*)&e1;
            l2a = __hadd2(l2a, e0);
            l2b = __hadd2(l2b, e1);
        }
        lr0 += __low2float(l2a) + __high2float(l2a);
        lr1 += __low2float(l2b) + __high2float(l2b);

        #pragma unroll
        for (int kk = 0; kk < 4; kk++) {
            uint32_t A[4] = { p0[2*kk], p1[2*kk], p0[2*kk + 1], p1[2*kk + 1] };
            #pragma unroll
            for (int np = 0; np < 4; np++) {
                uint32_t bv[4];
                ldm_x4_t(bv, vS + (uint32_t)(kk * 16) * ASTR * 2 + vRowOff + (uint32_t)(np * 16) * 2);
                mma16816h(o[2*np],     A, &bv[0]);
                mma16816h(o[2*np + 1], A, &bv[2]);
            }
        }
        __syncthreads();
    }

    lr0 += __shfl_xor_sync(0xffffffff, lr0, 1);
    lr0 += __shfl_xor_sync(0xffffffff, lr0, 2);
    lr1 += __shfl_xor_sync(0xffffffff, lr1, 1);
    lr1 += __shfl_xor_sync(0xffffffff, lr1, 2);
    float inv0 = 1.0f / lr0, inv1 = 1.0f / lr1;

    int gm0 = q0 + wid*16 + (lid >> 2);
    int gm1 = gm0 + 8;
    __half* r0p = aout + (size_t)(b * MM + gm0) * DD + h * DH;
    __half* r1p = aout + (size_t)(b * MM + gm1) * DD + h * DH;
    #pragma unroll
    for (int f = 0; f < 8; f++) {
        int c = 8*f + (lid & 3)*2;
        __half2 w0; w0.x = __float2half(o[f][0]*inv0); w0.y = __float2half(o[f][1]*inv0);
        __half2 w1; w1.x = __float2half(o[f][2]*inv1); w1.y = __float2half(o[f][3]*inv1);
        *(__half2*)(r0p + c) = w0;
        *(__half2*)(r1p + c) = w1;
    }
}

// ---------------- GeGLU f16 -> f16 ---------------------------------------------
__global__ void geglu_kernel(const __half* __restrict__ g, __half* __restrict__ act)
{
    int n = blockIdx.x;
    const __half2* gr = (const __half2*)(g + (size_t)n * WI_N);
    __half2* ar = (__half2*)(act + (size_t)n * FF);
    for (int f2 = threadIdx.x; f2 < FF/2; f2 += blockDim.x) {
        float2 x2 = __half22float2(gr[f2]);
        float2 gt = __half22float2(gr[f2 + FF/2]);
        float v0 = 0.5f * x2.x * (1.0f + erff(x2.x * 0.7071067811865476f)) * gt.x;
        float v1 = 0.5f * x2.y * (1.0f + erff(x2.y * 0.7071067811865476f)) * gt.y;
        __half2 hv; hv.x = __float2half(v0); hv.y = __float2half(v1);
        ar[f2] = hv;
    }
}

// ---------------- launch ------------------------------------------------------
extern "C" void kernel_launch(void* const* d_in, const int* in_sizes, int n_in,
                              void* d_out, int out_size)
{
    const float* hs     = (const float*)d_in[0];
    const int*   amask  = (const int*)  d_in[1];
    const float* ln1w   = (const float*)d_in[2];
    const float* ln1b   = (const float*)d_in[3];
    const float* wqkv_w = (const float*)d_in[4];
    const float* wqkv_b = (const float*)d_in[5];
    const float* wo_w   = (const float*)d_in[6];
    const float* ln2w   = (const float*)d_in[7];
    const float* ln2b   = (const float*)d_in[8];
    const float* wi_w   = (const float*)d_in[9];
    const float* womlp  = (const float*)d_in[10];
    float* out = (float*)d_out;

    float *xres;
    float2* rtab;
    __half *xh, *wh, *gg, *act, *q2, *k2, *v2;
    cudaGetSymbolAddress((void**)&xres, g_xres);
    cudaGetSymbolAddress((void**)&rtab, g_rope);
    cudaGetSymbolAddress((void**)&xh,   g_xh);
    cudaGetSymbolAddress((void**)&wh,   g_wh);
    cudaGetSymbolAddress((void**)&gg,   g_gg);
    cudaGetSymbolAddress((void**)&act,  g_act);
    cudaGetSymbolAddress((void**)&q2,   g_q2);
    cudaGetSymbolAddress((void**)&k2,   g_k2);
    cudaGetSymbolAddress((void**)&v2,   g_v2);

    cudaFuncSetAttribute(hgemm_kernel<0>, cudaFuncAttributeMaxDynamicSharedMemorySize, BG_SMEM);
    cudaFuncSetAttribute(hgemm_kernel<1>, cudaFuncAttributeMaxDynamicSharedMemorySize, BG_SMEM);
    cudaFuncSetAttribute(hgemm_kernel<2>, cudaFuncAttributeMaxDynamicSharedMemorySize, BG_SMEM);

    // 0. RoPE table
    ropetab_kernel<<<(MM*32)/256, 256>>>(rtab);

    // 1. LN1 -> xh (f16)
    ln_kernel<<<NTOK, 256>>>(hs, ln1w, ln1b, xh);

    // 2. QKV gemm (f16, K=1024) -> q2/k2/v2 f16
    cvth_kernel<<<(QKV_N*DD + 255)/256, 256>>>(wqkv_w, wh, QKV_N*DD);
    hgemm_kernel<1><<<dim3(QKV_N/128, NTOK/128), 256, BG_SMEM>>>(
        xh, wh, wqkv_b, nullptr, nullptr, nullptr, q2, k2, v2, QKV_N, DD);

    // 3. RoPE in-place on q2,k2
    rope_kernel<<<(BB*HH*MM*32)/256, 256>>>(q2, k2, rtab);

    // 4. Flash attention -> xh (f16 attention output, token-major)
    attn_kernel<<<dim3(MM/64, BB*HH), 128>>>(q2, k2, v2, amask, xh);

    // 5. O projection (f16, K=1024) + fp32 residual -> xres
    cvth_kernel<<<(DD*DD + 255)/256, 256>>>(wo_w, wh, DD*DD);
    hgemm_kernel<2><<<dim3(DD/128, NTOK/128), 256, BG_SMEM>>>(
        xh, wh, nullptr, hs, xres, nullptr, nullptr, nullptr, nullptr, DD, DD);

    // 6. LN2 -> xh (f16)
    ln_kernel<<<NTOK, 256>>>(xres, ln2w, ln2b, xh);

    // 7. Wi gemm (f16, K=1024) -> gg f16
    cvth_kernel<<<(WI_N*DD + 255)/256, 256>>>(wi_w, wh, WI_N*DD);
    hgemm_kernel<0><<<dim3(WI_N/128, NTOK/128), 256, BG_SMEM>>>(
        xh, wh, nullptr, nullptr, nullptr, gg, nullptr, nullptr, nullptr, WI_N, DD);

    // 8. GeGLU -> act f16
    geglu_kernel<<<NTOK, 256>>>(gg, act);

    // 9. Wo_mlp gemm (f16, K=2624) + fp32 residual -> out
    cvth_kernel<<<(DD*FF + 255)/256, 256>>>(womlp, wh, DD*FF);
    hgemm_kernel<2><<<dim3(DD/128, NTOK/128), 256, BG_SMEM>>>(
        act, wh, nullptr, xres, out, nullptr, nullptr, nullptr, nullptr, DD, FF);
}